// round 7
// baseline (speedup 1.0000x reference)
#include <cuda_runtime.h>
#include <cfloat>

#define Bn 512
#define Tn 512
#define Kn 64
#define PD 8  // potentials prefetch ring depth (registers)

__device__ int g_seq[Bn];

// Monotone float <-> uint order-preserving map (finite floats).
__device__ __forceinline__ unsigned fmap(float f) {
    int i = __float_as_int(f);
    return (unsigned)(i >= 0 ? (i ^ 0x80000000) : ~i);
}
__device__ __forceinline__ float funmap(unsigned u) {
    int i = (u & 0x80000000u) ? (int)(u ^ 0x80000000u) : ~(int)u;
    return __int_as_float(i);
}

// ---------------------------------------------------------------------------
// Kernel 1: seq_lens[b] = int( mean_k( sum_t (x[b,t,k] != 0) ) )  (exact)
// ---------------------------------------------------------------------------
__global__ __launch_bounds__(256) void seqlen_kernel(const float* __restrict__ x) {
    __shared__ int red[256];
    const int b = blockIdx.x;
    const float4* xb = (const float4*)(x + (size_t)b * Tn * Kn);
    int c = 0;
    for (int i = threadIdx.x; i < (Tn * Kn) / 4; i += 256) {
        float4 v = xb[i];
        c += (v.x != 0.0f) + (v.y != 0.0f) + (v.z != 0.0f) + (v.w != 0.0f);
    }
    red[threadIdx.x] = c;
    __syncthreads();
    for (int s = 128; s > 0; s >>= 1) {
        if (threadIdx.x < s) red[threadIdx.x] += red[threadIdx.x + s];
        __syncthreads();
    }
    if (threadIdx.x == 0) g_seq[b] = red[0] >> 6;  // floor(total / 64)
}

// ---------------------------------------------------------------------------
// Exact full 64-candidate scan (fallback / slow path). First max wins.
// ---------------------------------------------------------------------------
__device__ __noinline__ void full_scan64(
    float a_lo, float a_hi, const float2* trans2, int l,
    float& best0, float& best1, int& bi0, int& bi1)
{
    float b0 = -FLT_MAX, b1 = -FLT_MAX;
    int x0 = 0, x1 = 0;
#pragma unroll 4
    for (int i = 0; i < Kn; i++) {
        const float asel = (i < 32) ? a_lo : a_hi;
        const float av = __shfl_sync(0xffffffffu, asel, i & 31);
        const float2 tv = trans2[i * 32 + l];
        const float s0 = av + tv.x, s1 = av + tv.y;
        const bool g0 = s0 > b0; b0 = g0 ? s0 : b0; x0 = g0 ? i : x0;
        const bool g1 = s1 > b1; b1 = g1 ? s1 : b1; x1 = g1 ? i : x1;
    }
    best0 = b0; best1 = b1; bi0 = x0; bi1 = x1;
}

// Candidate fetch: alpha[i] via shuffle (uniform lane), trans column pair.
#define FETCH(i_, s0_, s1_)                                                 \
    {                                                                       \
        const float asel_ = ((i_) < 32) ? a_lo : a_hi;                      \
        const float av_ = __shfl_sync(0xffffffffu, asel_, (i_) & 31);       \
        const float2 tv_ = trans2[(i_) * 32 + l];                           \
        s0_ = av_ + tv_.x;                                                  \
        s1_ = av_ + tv_.y;                                                  \
    }

// One branchless DP step (fast path, t < sl guaranteed). Slot S_ compile-time.
#define STEP_F(T_, S_)                                                       \
    {                                                                        \
        const int t_ = (T_);                                                 \
        const float p_lo = plo[S_];                                          \
        const float p_hi = phi[S_];                                          \
        {                                                                    \
            const int tl_ = (t_ + PD <= Tn - 1) ? (t_ + PD) : (Tn - 1);      \
            plo[S_] = pb[tl_ * Kn + l];                                      \
            phi[S_] = pb[tl_ * Kn + 32 + l];                                 \
        }                                                                    \
        const unsigned long long M =                                         \
            ((unsigned long long)m_hi << 32) | (unsigned long long)m_lo;     \
        float best0, best1;                                                  \
        int bi0, bi1;                                                        \
        if (__popcll(M) <= 8) {                                              \
            /* 4 lowest candidates (ascending), duplicate-pad on empty */    \
            const int i0 = __ffsll((long long)M) - 1;                        \
            unsigned long long Mx = M & (M - 1);                             \
            const int i1 = Mx ? __ffsll((long long)Mx) - 1 : i0;             \
            Mx &= Mx - 1;                                                    \
            const int i2 = Mx ? __ffsll((long long)Mx) - 1 : i1;             \
            Mx &= Mx - 1;                                                    \
            const int i3 = Mx ? __ffsll((long long)Mx) - 1 : i2;             \
            /* 4 highest candidates (descending), duplicate-pad on empty */  \
            const int j0 = 63 - __clzll((long long)M);                       \
            unsigned long long My = M & ~(1ull << j0);                       \
            const int j1 = My ? 63 - __clzll((long long)My) : j0;            \
            My &= ~(1ull << j1);                                             \
            const int j2 = My ? 63 - __clzll((long long)My) : j1;            \
            My &= ~(1ull << j2);                                             \
            const int j3 = My ? 63 - __clzll((long long)My) : j2;            \
            float sa0, sb0, sa1, sb1, sa2, sb2, sa3, sb3;                    \
            float ta0, tb0, ta1, tb1, ta2, tb2, ta3, tb3;                    \
            FETCH(i0, sa0, sb0); FETCH(i1, sa1, sb1);                        \
            FETCH(i2, sa2, sb2); FETCH(i3, sa3, sb3);                        \
            FETCH(j0, ta0, tb0); FETCH(j1, ta1, tb1);                        \
            FETCH(j2, ta2, tb2); FETCH(j3, ta3, tb3);                        \
            /* chain A: ascending, strict > -> first max wins inside A */    \
            float bA0 = sa0, bA1 = sb0; int xA0 = i0, xA1 = i0;              \
            { const bool g = sa1 > bA0; bA0 = g?sa1:bA0; xA0 = g?i1:xA0; }   \
            { const bool g = sb1 > bA1; bA1 = g?sb1:bA1; xA1 = g?i1:xA1; }   \
            { const bool g = sa2 > bA0; bA0 = g?sa2:bA0; xA0 = g?i2:xA0; }   \
            { const bool g = sb2 > bA1; bA1 = g?sb2:bA1; xA1 = g?i2:xA1; }   \
            { const bool g = sa3 > bA0; bA0 = g?sa3:bA0; xA0 = g?i3:xA0; }   \
            { const bool g = sb3 > bA1; bA1 = g?sb3:bA1; xA1 = g?i3:xA1; }   \
            /* chain B: descending, >= -> smallest index wins ties in B */   \
            float bB0 = ta0, bB1 = tb0; int xB0 = j0, xB1 = j0;              \
            { const bool g = ta1 >= bB0; bB0 = g?ta1:bB0; xB0 = g?j1:xB0; }  \
            { const bool g = tb1 >= bB1; bB1 = g?tb1:bB1; xB1 = g?j1:xB1; }  \
            { const bool g = ta2 >= bB0; bB0 = g?ta2:bB0; xB0 = g?j2:xB0; }  \
            { const bool g = tb2 >= bB1; bB1 = g?tb2:bB1; xB1 = g?j2:xB1; }  \
            { const bool g = ta3 >= bB0; bB0 = g?ta3:bB0; xB0 = g?j3:xB0; }  \
            { const bool g = tb3 >= bB1; bB1 = g?tb3:bB1; xB1 = g?j3:xB1; }  \
            /* merge: A (lower indices) wins ties (strict > from B) */       \
            { const bool g = bB0 > bA0; best0 = g?bB0:bA0; bi0 = g?xB0:xA0; }\
            { const bool g = bB1 > bA1; best1 = g?bB1:bA1; bi1 = g?xB1:xA1; }\
        } else {                                                             \
            full_scan64(a_lo, a_hi, trans2, l, best0, best1, bi0, bi1);      \
        }                                                                    \
        a_lo = p_lo + best0;                                                 \
        a_hi = p_hi + best1;                                                 \
        bp[(t_ - 1) * Kn + l] = (unsigned char)bi0;                          \
        bp[(t_ - 1) * Kn + 32 + l] = (unsigned char)bi1;                     \
        const unsigned am_ = fmap(a_lo), ah_ = fmap(a_hi);                   \
        const unsigned wm_ =                                                 \
            __reduce_max_sync(0xffffffffu, am_ > ah_ ? am_ : ah_);           \
        const float thr_ = funmap(wm_) - rT;                                 \
        m_lo = __ballot_sync(0xffffffffu, a_lo >= thr_);                     \
        m_hi = __ballot_sync(0xffffffffu, a_hi >= thr_);                     \
    }

// ---------------------------------------------------------------------------
// Kernel 2: single-warp Viterbi, branchless pruned step.
// Pruning: candidates = { i : alpha[i] >= max(alpha) - rT }; excluded i lose
// STRICTLY for every to-tag, so first-max over candidates == full argmax.
// ---------------------------------------------------------------------------
__global__ __launch_bounds__(32) void viterbi_kernel(
    const float* __restrict__ pots,   // [B, T, K]
    const float* __restrict__ trans,  // [K, K]
    float* __restrict__ out)          // [B, T] float32
{
    extern __shared__ float2 trans2[];            // [64][32]: (T[i][l], T[i][l+32])
    __shared__ unsigned char bp[(Tn - 1) * Kn];   // 32704 B
    __shared__ unsigned char tags[Tn];
    __shared__ float alpha_f[Kn];

    const int b = blockIdx.x;
    const int l = threadIdx.x;  // lane; owns to-tags l and l+32

    // ---- Prologue: stage transitions (float2-packed) + padded range ----
    const float4* tr4 = (const float4*)trans;
    float tmin = FLT_MAX, tmax = -FLT_MAX;
#pragma unroll
    for (int q = 0; q < 32; q++) {
        const int idx = q * 32 + l;
        const float4 v = tr4[idx];
        tmin = fminf(tmin, fminf(fminf(v.x, v.y), fminf(v.z, v.w)));
        tmax = fmaxf(tmax, fmaxf(fmaxf(v.x, v.y), fmaxf(v.z, v.w)));
        const int base = idx * 4;
        const int i = base >> 6;
        const int c = base & 63;
        if (c < 32) {
            trans2[i * 32 + c + 0].x = v.x;
            trans2[i * 32 + c + 1].x = v.y;
            trans2[i * 32 + c + 2].x = v.z;
            trans2[i * 32 + c + 3].x = v.w;
        } else {
            const int cc = c - 32;
            trans2[i * 32 + cc + 0].y = v.x;
            trans2[i * 32 + cc + 1].y = v.y;
            trans2[i * 32 + cc + 2].y = v.z;
            trans2[i * 32 + cc + 3].y = v.w;
        }
    }
    const unsigned rmn = __reduce_min_sync(0xffffffffu, fmap(tmin));
    const unsigned rmx = __reduce_max_sync(0xffffffffu, fmap(tmax));
    const float r = funmap(rmx) - funmap(rmn);
    const float rT = r + fabsf(r) * 1e-5f + 0.01f;  // pad only ADDS candidates
    __syncwarp();

    const float* pb = pots + (size_t)b * Tn * Kn;
    int sl = g_seq[b];
    if (sl > Tn) sl = Tn;

    float a_lo = pb[l];
    float a_hi = pb[32 + l];

    if (sl >= Tn) {
        // ---------------- FAST PATH: every step active, branch-free ----------
        unsigned m_lo, m_hi;
        {
            const unsigned am = fmap(a_lo), ah = fmap(a_hi);
            const unsigned wm = __reduce_max_sync(0xffffffffu, am > ah ? am : ah);
            const float thr = funmap(wm) - rT;
            m_lo = __ballot_sync(0xffffffffu, a_lo >= thr);
            m_hi = __ballot_sync(0xffffffffu, a_hi >= thr);
        }
        float plo[PD], phi[PD];
#pragma unroll
        for (int d = 1; d <= PD; d++) {
            plo[d & (PD - 1)] = pb[d * Kn + l];
            phi[d & (PD - 1)] = pb[d * Kn + 32 + l];
        }
        int t = 1;
#pragma unroll 1
        for (int tb = 0; tb < 63; tb++) {
            STEP_F(t + 0, 1); STEP_F(t + 1, 2); STEP_F(t + 2, 3); STEP_F(t + 3, 4);
            STEP_F(t + 4, 5); STEP_F(t + 5, 6); STEP_F(t + 6, 7); STEP_F(t + 7, 0);
            t += 8;
        }
        STEP_F(t + 0, 1); STEP_F(t + 1, 2); STEP_F(t + 2, 3); STEP_F(t + 3, 4);
        STEP_F(t + 4, 5); STEP_F(t + 5, 6); STEP_F(t + 6, 7);
    } else {
        // ---------------- GENERAL PATH (rare): exact full scan ---------------
#pragma unroll 1
        for (int t = 1; t < Tn; t++) {
            if (t < sl) {
                float best0, best1; int bi0, bi1;
                full_scan64(a_lo, a_hi, trans2, l, best0, best1, bi0, bi1);
                a_lo = pb[t * Kn + l] + best0;
                a_hi = pb[t * Kn + 32 + l] + best1;
                bp[(t - 1) * Kn + l] = (unsigned char)bi0;
                bp[(t - 1) * Kn + 32 + l] = (unsigned char)bi1;
            } else {
                bp[(t - 1) * Kn + l] = (unsigned char)l;
                bp[(t - 1) * Kn + 32 + l] = (unsigned char)(32 + l);
            }
        }
    }

    // Final alpha -> smem for the backtrace scan
    alpha_f[l] = a_lo;
    alpha_f[32 + l] = a_hi;
    __syncwarp();

    // Backtrace (smem pointer-chase) by lane 0. First max wins.
    if (l == 0) {
        float bv = alpha_f[0];
        int bt = 0;
#pragma unroll 1
        for (int i = 1; i < Kn; i++) {
            const float v = alpha_f[i];
            if (v > bv) { bv = v; bt = i; }
        }
        int tg = bt;
        tags[Tn - 1] = (unsigned char)tg;
#pragma unroll 1
        for (int tt = Tn - 2; tt >= 0; tt--) {
            tg = bp[tt * Kn + tg];
            tags[tt] = (unsigned char)tg;
        }
    }
    __syncwarp();

    // Coalesced float32 output write (16 per lane).
    float* ob = out + (size_t)b * Tn;
#pragma unroll
    for (int tt = l; tt < Tn; tt += 32) ob[tt] = (float)tags[tt];
}

// ---------------------------------------------------------------------------
extern "C" void kernel_launch(void* const* d_in, const int* in_sizes, int n_in,
                              void* d_out, int out_size) {
    const float* inputs = nullptr;
    const float* transitions = nullptr;
    for (int i = 0; i < n_in; i++) {
        if (in_sizes[i] == Kn * Kn) transitions = (const float*)d_in[i];
        else if (in_sizes[i] == Bn * Tn * Kn) inputs = (const float*)d_in[i];
    }
    if (!inputs) inputs = (const float*)d_in[0];
    if (!transitions) transitions = (const float*)d_in[1];

    float* out = (float*)d_out;

    // Static (~33.5 KB) + 16 KB dynamic -> opt in (host config, capture-safe).
    cudaFuncSetAttribute(viterbi_kernel,
                         cudaFuncAttributeMaxDynamicSharedMemorySize,
                         Kn * 32 * (int)sizeof(float2));

    seqlen_kernel<<<Bn, 256>>>(inputs);
    viterbi_kernel<<<Bn, 32, Kn * 32 * sizeof(float2)>>>(inputs, transitions, out);
}

// round 8
// speedup vs baseline: 1.7430x; 1.7430x over previous
#include <cuda_runtime.h>
#include <cfloat>

#define Bn 512
#define Tn 512
#define Kn 64
#define PD 8  // potentials prefetch ring depth (registers)

__device__ int g_seq[Bn];

// Monotone float <-> uint order-preserving map (finite floats).
__device__ __forceinline__ unsigned fmap(float f) {
    int i = __float_as_int(f);
    return (unsigned)(i >= 0 ? (i ^ 0x80000000) : ~i);
}
__device__ __forceinline__ float funmap(unsigned u) {
    int i = (u & 0x80000000u) ? (int)(u ^ 0x80000000u) : ~(int)u;
    return __int_as_float(i);
}

// ---------------------------------------------------------------------------
// Kernel 1: seq_lens[b] = int( mean_k( sum_t (x[b,t,k] != 0) ) )  (exact)
// ---------------------------------------------------------------------------
__global__ __launch_bounds__(256) void seqlen_kernel(const float* __restrict__ x) {
    __shared__ int red[256];
    const int b = blockIdx.x;
    const float4* xb = (const float4*)(x + (size_t)b * Tn * Kn);
    int c = 0;
    for (int i = threadIdx.x; i < (Tn * Kn) / 4; i += 256) {
        float4 v = xb[i];
        c += (v.x != 0.0f) + (v.y != 0.0f) + (v.z != 0.0f) + (v.w != 0.0f);
    }
    red[threadIdx.x] = c;
    __syncthreads();
    for (int s = 128; s > 0; s >>= 1) {
        if (threadIdx.x < s) red[threadIdx.x] += red[threadIdx.x + s];
        __syncthreads();
    }
    if (threadIdx.x == 0) g_seq[b] = red[0] >> 6;  // floor(total / 64)
}

// ---------------------------------------------------------------------------
// Exact full 64-candidate scan (general path). First max wins.
// ---------------------------------------------------------------------------
__device__ __noinline__ void full_scan64(
    float a_lo, float a_hi, const float2* trans2, int l,
    float& best0, float& best1, int& bi0, int& bi1)
{
    float b0 = -FLT_MAX, b1 = -FLT_MAX;
    int x0 = 0, x1 = 0;
#pragma unroll 4
    for (int i = 0; i < Kn; i++) {
        const float asel = (i < 32) ? a_lo : a_hi;
        const float av = __shfl_sync(0xffffffffu, asel, i & 31);
        const float2 tv = trans2[i * 32 + l];
        const float s0 = av + tv.x, s1 = av + tv.y;
        const bool g0 = s0 > b0; b0 = g0 ? s0 : b0; x0 = g0 ? i : x0;
        const bool g1 = s1 > b1; b1 = g1 ? s1 : b1; x1 = g1 ? i : x1;
    }
    best0 = b0; best1 = b1; bi0 = x0; bi1 = x1;
}

// Candidate fetch: alpha[i] via shuffle (uniform lane), trans column pair.
#define FETCH(i_, s0_, s1_)                                                 \
    {                                                                       \
        const float asel_ = ((i_) < 32) ? a_lo : a_hi;                      \
        const float av_ = __shfl_sync(0xffffffffu, asel_, (i_) & 31);       \
        const float2 tv_ = trans2[(i_) * 32 + l];                           \
        s0_ = av_ + tv_.x;                                                  \
        s1_ = av_ + tv_.y;                                                  \
    }

// One DP step (fast path, t < sl guaranteed). Ring slot S_ is compile-time.
// First 4 candidates (ascending, duplicate-padded) handled branch-free;
// rare C>4 remainder via uniform loop (still ascending + strict >).
#define STEP_F(T_, S_)                                                       \
    {                                                                        \
        const int t_ = (T_);                                                 \
        const float p_lo = plo[S_];                                          \
        const float p_hi = phi[S_];                                          \
        {                                                                    \
            const int tl_ = (t_ + PD <= Tn - 1) ? (t_ + PD) : (Tn - 1);      \
            plo[S_] = pb[tl_ * Kn + l];                                      \
            phi[S_] = pb[tl_ * Kn + 32 + l];                                 \
        }                                                                    \
        const unsigned long long M =                                         \
            ((unsigned long long)m_hi << 32) | (unsigned long long)m_lo;     \
        /* 4 lowest candidates, ascending, duplicate-padded when C<4 */      \
        const int i0 = __ffsll((long long)M) - 1;                            \
        unsigned long long Mx = M & (M - 1);                                 \
        const int i1 = Mx ? __ffsll((long long)Mx) - 1 : i0;                 \
        Mx &= Mx - 1;                                                        \
        const int i2 = Mx ? __ffsll((long long)Mx) - 1 : i1;                 \
        Mx &= Mx - 1;                                                        \
        const int i3 = Mx ? __ffsll((long long)Mx) - 1 : i2;                 \
        unsigned long long Mrest = Mx & (Mx - 1);                            \
        float sa0, sb0, sa1, sb1, sa2, sb2, sa3, sb3;                        \
        FETCH(i0, sa0, sb0); FETCH(i1, sa1, sb1);                            \
        FETCH(i2, sa2, sb2); FETCH(i3, sa3, sb3);                            \
        /* ascending chain, strict > : first max wins (dups are no-ops) */   \
        float best0 = sa0, best1 = sb0;                                      \
        int bi0 = i0, bi1 = i0;                                              \
        { const bool g = sa1 > best0; best0 = g?sa1:best0; bi0 = g?i1:bi0; } \
        { const bool g = sb1 > best1; best1 = g?sb1:best1; bi1 = g?i1:bi1; } \
        { const bool g = sa2 > best0; best0 = g?sa2:best0; bi0 = g?i2:bi0; } \
        { const bool g = sb2 > best1; best1 = g?sb2:best1; bi1 = g?i2:bi1; } \
        { const bool g = sa3 > best0; best0 = g?sa3:best0; bi0 = g?i3:bi0; } \
        { const bool g = sb3 > best1; best1 = g?sb3:best1; bi1 = g?i3:bi1; } \
        if (Mrest) { /* rare: C > 4; continue ascending, exact */            \
            do {                                                             \
                const int i_ = __ffsll((long long)Mrest) - 1;                \
                Mrest &= Mrest - 1;                                          \
                float s0_, s1_;                                              \
                FETCH(i_, s0_, s1_);                                         \
                { const bool g = s0_ > best0;                                \
                  best0 = g ? s0_ : best0;  bi0 = g ? i_ : bi0; }            \
                { const bool g = s1_ > best1;                                \
                  best1 = g ? s1_ : best1;  bi1 = g ? i_ : bi1; }            \
            } while (Mrest);                                                 \
        }                                                                    \
        a_lo = p_lo + best0;                                                 \
        a_hi = p_hi + best1;                                                 \
        bp[(t_ - 1) * Kn + l] = (unsigned char)bi0;                          \
        bp[(t_ - 1) * Kn + 32 + l] = (unsigned char)bi1;                     \
        const unsigned am_ = fmap(a_lo), ah_ = fmap(a_hi);                   \
        const unsigned wm_ =                                                 \
            __reduce_max_sync(0xffffffffu, am_ > ah_ ? am_ : ah_);           \
        const float thr_ = funmap(wm_) - rT;                                 \
        m_lo = __ballot_sync(0xffffffffu, a_lo >= thr_);                     \
        m_hi = __ballot_sync(0xffffffffu, a_hi >= thr_);                     \
    }

// ---------------------------------------------------------------------------
// Kernel 2: single-warp Viterbi with pruned step.
// Candidates = { i : alpha[i] >= max(alpha) - rT }; excluded i lose STRICTLY
// for every to-tag, so first-max over candidates == full jnp.argmax.
// ---------------------------------------------------------------------------
__global__ __launch_bounds__(32) void viterbi_kernel(
    const float* __restrict__ pots,   // [B, T, K]
    const float* __restrict__ trans,  // [K, K]
    float* __restrict__ out)          // [B, T] float32
{
    extern __shared__ float2 trans2[];            // [64][32]: (T[i][l], T[i][l+32])
    __shared__ unsigned char bp[(Tn - 1) * Kn];   // 32704 B
    __shared__ unsigned char tags[Tn];
    __shared__ float alpha_f[Kn];

    const int b = blockIdx.x;
    const int l = threadIdx.x;  // lane; owns to-tags l and l+32

    // ---- Prologue: stage transitions (float2-packed) + padded range ----
    const float4* tr4 = (const float4*)trans;
    float tmin = FLT_MAX, tmax = -FLT_MAX;
#pragma unroll
    for (int q = 0; q < 32; q++) {
        const int idx = q * 32 + l;
        const float4 v = tr4[idx];
        tmin = fminf(tmin, fminf(fminf(v.x, v.y), fminf(v.z, v.w)));
        tmax = fmaxf(tmax, fmaxf(fmaxf(v.x, v.y), fmaxf(v.z, v.w)));
        const int base = idx * 4;
        const int i = base >> 6;
        const int c = base & 63;
        if (c < 32) {
            trans2[i * 32 + c + 0].x = v.x;
            trans2[i * 32 + c + 1].x = v.y;
            trans2[i * 32 + c + 2].x = v.z;
            trans2[i * 32 + c + 3].x = v.w;
        } else {
            const int cc = c - 32;
            trans2[i * 32 + cc + 0].y = v.x;
            trans2[i * 32 + cc + 1].y = v.y;
            trans2[i * 32 + cc + 2].y = v.z;
            trans2[i * 32 + cc + 3].y = v.w;
        }
    }
    const unsigned rmn = __reduce_min_sync(0xffffffffu, fmap(tmin));
    const unsigned rmx = __reduce_max_sync(0xffffffffu, fmap(tmax));
    const float r = funmap(rmx) - funmap(rmn);
    const float rT = r + fabsf(r) * 1e-5f + 0.01f;  // pad only ADDS candidates
    __syncwarp();

    const float* pb = pots + (size_t)b * Tn * Kn;
    int sl = g_seq[b];
    if (sl > Tn) sl = Tn;

    float a_lo = pb[l];
    float a_hi = pb[32 + l];

    if (sl >= Tn) {
        // ---------------- FAST PATH: every step active ----------------------
        unsigned m_lo, m_hi;
        {
            const unsigned am = fmap(a_lo), ah = fmap(a_hi);
            const unsigned wm = __reduce_max_sync(0xffffffffu, am > ah ? am : ah);
            const float thr = funmap(wm) - rT;
            m_lo = __ballot_sync(0xffffffffu, a_lo >= thr);
            m_hi = __ballot_sync(0xffffffffu, a_hi >= thr);
        }
        float plo[PD], phi[PD];
#pragma unroll
        for (int d = 1; d <= PD; d++) {
            plo[d & (PD - 1)] = pb[d * Kn + l];
            phi[d & (PD - 1)] = pb[d * Kn + 32 + l];
        }
        int t = 1;
#pragma unroll 1
        for (int tb = 0; tb < 63; tb++) {
            STEP_F(t + 0, 1); STEP_F(t + 1, 2); STEP_F(t + 2, 3); STEP_F(t + 3, 4);
            STEP_F(t + 4, 5); STEP_F(t + 5, 6); STEP_F(t + 6, 7); STEP_F(t + 7, 0);
            t += 8;
        }
        STEP_F(t + 0, 1); STEP_F(t + 1, 2); STEP_F(t + 2, 3); STEP_F(t + 3, 4);
        STEP_F(t + 4, 5); STEP_F(t + 5, 6); STEP_F(t + 6, 7);
    } else {
        // ---------------- GENERAL PATH (rare): exact full scan ---------------
#pragma unroll 1
        for (int t = 1; t < Tn; t++) {
            if (t < sl) {
                float best0, best1; int bi0, bi1;
                full_scan64(a_lo, a_hi, trans2, l, best0, best1, bi0, bi1);
                a_lo = pb[t * Kn + l] + best0;
                a_hi = pb[t * Kn + 32 + l] + best1;
                bp[(t - 1) * Kn + l] = (unsigned char)bi0;
                bp[(t - 1) * Kn + 32 + l] = (unsigned char)bi1;
            } else {
                bp[(t - 1) * Kn + l] = (unsigned char)l;
                bp[(t - 1) * Kn + 32 + l] = (unsigned char)(32 + l);
            }
        }
    }

    // Final alpha -> smem for the backtrace scan
    alpha_f[l] = a_lo;
    alpha_f[32 + l] = a_hi;
    __syncwarp();

    // Backtrace (smem pointer-chase) by lane 0. First max wins.
    if (l == 0) {
        float bv = alpha_f[0];
        int bt = 0;
#pragma unroll 1
        for (int i = 1; i < Kn; i++) {
            const float v = alpha_f[i];
            if (v > bv) { bv = v; bt = i; }
        }
        int tg = bt;
        tags[Tn - 1] = (unsigned char)tg;
#pragma unroll 1
        for (int tt = Tn - 2; tt >= 0; tt--) {
            tg = bp[tt * Kn + tg];
            tags[tt] = (unsigned char)tg;
        }
    }
    __syncwarp();

    // Coalesced float32 output write (16 per lane).
    float* ob = out + (size_t)b * Tn;
#pragma unroll
    for (int tt = l; tt < Tn; tt += 32) ob[tt] = (float)tags[tt];
}

// ---------------------------------------------------------------------------
extern "C" void kernel_launch(void* const* d_in, const int* in_sizes, int n_in,
                              void* d_out, int out_size) {
    const float* inputs = nullptr;
    const float* transitions = nullptr;
    for (int i = 0; i < n_in; i++) {
        if (in_sizes[i] == Kn * Kn) transitions = (const float*)d_in[i];
        else if (in_sizes[i] == Bn * Tn * Kn) inputs = (const float*)d_in[i];
    }
    if (!inputs) inputs = (const float*)d_in[0];
    if (!transitions) transitions = (const float*)d_in[1];

    float* out = (float*)d_out;

    // Static (~33.5 KB) + 16 KB dynamic -> opt in (host config, capture-safe).
    cudaFuncSetAttribute(viterbi_kernel,
                         cudaFuncAttributeMaxDynamicSharedMemorySize,
                         Kn * 32 * (int)sizeof(float2));

    seqlen_kernel<<<Bn, 256>>>(inputs);
    viterbi_kernel<<<Bn, 32, Kn * 32 * sizeof(float2)>>>(inputs, transitions, out);
}